// round 15
// baseline (speedup 1.0000x reference)
#include <cuda_runtime.h>
#include <math.h>
#include <stdint.h>

// VIN full-grid 8-CTA cluster, 1024 threads/CTA: the 8-row band is exactly
// 8 rows x 32 col-pairs x 4 lanes = 1024 tasks -> ONE pass per sweep (no
// task loops, no predicates). 4 lanes per cell-pair, 2 actions per lane
// (18 packed f32x2 weight u64 = 36 regs, register-resident). Per-iteration
// halo exchange via st.shared::cluster + remote mbarrier.arrive.release
// (proven R5/R12); triple-buffered v makes cross-CTA skew-1 safe. Halos
// pushed on the final sweep too + closing cluster_sync so band-edge queries
// read exact v19. Only batch 0 reaches the output; the 150-ch hidden conv
// collapses into a 2-ch 3x3 effective conv; qr precomputed once.

#define NCL 8                  // cluster CTAs
#define RPC 8                  // own rows per CTA
#define PW 66                  // padded row stride
#define LROWS 10               // band + 2 halo rows
#define XROWS 12               // X rows rbase-2 .. rbase+9
#define NTH 1024
#define NSWEEP 19
#define QSTR 516               // u64 per sub plane: 8*32*2 + 4 pad

__device__ __forceinline__ uint32_t s2u(const void* p) {
    return (uint32_t)__cvta_generic_to_shared(p);
}
__device__ __forceinline__ uint64_t pack2(float x, float y) {
    uint64_t r;
    asm("mov.b64 %0, {%1, %2};" : "=l"(r) : "f"(x), "f"(y));
    return r;
}
__device__ __forceinline__ float2 unpack2(uint64_t v) {
    float2 f;
    asm("mov.b64 {%0, %1}, %2;" : "=f"(f.x), "=f"(f.y) : "l"(v));
    return f;
}
__device__ __forceinline__ uint64_t fma2(uint64_t a, uint64_t b, uint64_t c) {
    uint64_t d;
    asm("fma.rn.f32x2 %0, %1, %2, %3;" : "=l"(d) : "l"(a), "l"(b), "l"(c));
    return d;
}
__device__ __forceinline__ void cluster_sync() {
    asm volatile("barrier.cluster.arrive.aligned;" ::: "memory");
    asm volatile("barrier.cluster.wait.aligned;" ::: "memory");
}
__device__ __forceinline__ void halo_out1(uint32_t laddr, uint32_t rank,
                                          float v, uint32_t lmbar) {
    asm volatile(
        "{\n\t.reg .b32 ra, rb;\n\t"
        "mapa.shared::cluster.u32 ra, %0, %1;\n\t"
        "st.shared::cluster.f32 [ra], %2;\n\t"
        "mapa.shared::cluster.u32 rb, %3, %1;\n\t"
        "mbarrier.arrive.release.cluster.shared::cluster.b64 _, [rb];\n\t}"
        :: "r"(laddr), "r"(rank), "f"(v), "r"(lmbar) : "memory");
}
__device__ __forceinline__ void mbar_wait(uint32_t addr, uint32_t parity) {
    asm volatile(
        "{\n\t.reg .pred P;\n\t"
        "W%=:\n\t"
        "mbarrier.try_wait.parity.acquire.cluster.shared::cta.b64 P, [%0], %1, 0x989680;\n\t"
        "@P bra D%=;\n\t"
        "bra W%=;\n\t"
        "D%=:\n\t}"
        :: "r"(addr), "r"(parity) : "memory");
}

__global__ __launch_bounds__(NTH, 1) __cluster_dims__(NCL, 1, 1)
void vin_kernel(const float* __restrict__ X,
                const int* __restrict__ S1,
                const int* __restrict__ S2,
                const float* __restrict__ Wh,
                const float* __restrict__ bh,
                const float* __restrict__ Wr,
                const float* __restrict__ Wq,
                float* __restrict__ out)
{
    __shared__ __align__(16) unsigned long long qr2[4 * QSTR];  // [sub][row][pair][2]
    __shared__ float Xs[2 * XROWS * PW];
    __shared__ float rp[LROWS * PW];
    __shared__ float vbuf[3][LROWS * PW];
    __shared__ float wqs[144];
    __shared__ float part[19 * 8];
    __shared__ float weff[19];
    __shared__ unsigned long long mbar;

    const int t = threadIdx.x;
    const int rank = blockIdx.x;
    const int rbase = rank * RPC;
    const int sub = t & 3;                 // lane-in-task: actions 2sub, 2sub+1
    const int p = (t >> 2) & 31;           // pair: global cols 2p, 2p+1
    const int row = t >> 7;                // band row 0..7
    const uint64_t* qr2s = (const uint64_t*)qr2 + sub * QSTR;
    const uint32_t mb = s2u(&mbar);

    // task geometry, fully precomputed
    const int roff = row * PW + 2 * p;               // read base (buffer rows row..row+2)
    const unsigned qoff = (unsigned)((row * 32 + p) * 2);
    const int soff = (row + 1) * PW + 1 + 2 * p + sub;
    const bool isTop = (row == 0) && (rank > 0);
    const bool isBot = (row == RPC - 1) && (rank < NCL - 1);
    const bool waiter = ((row == 0) && (rank > 0)) ||
                        ((row == RPC - 1) && (rank < NCL - 1));
    const int roffRT = 9 * PW + 1 + 2 * p + sub;     // upper nbr's bottom halo
    const int roffRB = 1 + 2 * p + sub;              // lower nbr's top halo

    // ---- init ----
    for (int i = t; i < LROWS * PW; i += NTH) {
        vbuf[0][i] = 0.f; vbuf[1][i] = 0.f; vbuf[2][i] = 0.f; rp[i] = 0.f;
    }
    if (t < 144) wqs[t] = Wq[t];
    if (t < 152) {
        int pp = t >> 3, c = t & 7;
        float s = 0.f;
        for (int h = c; h < 150; h += 8)
            s += Wr[h] * (pp < 18 ? Wh[h * 18 + pp] : bh[h]);
        part[pp * 8 + c] = s;
    }
    if (t == 0) {
        int nb = (rank > 0) + (rank < NCL - 1);
        asm volatile("mbarrier.init.shared.b64 [%0], %1;"
                     :: "r"(mb), "r"(64 * nb) : "memory");
    }
    __syncthreads();
    if (t < 19) {
        float s = 0.f;
        #pragma unroll
        for (int c = 0; c < 8; c++) s += part[t * 8 + c];
        weff[t] = s;
    }
    // ---- X band rows rbase-2..rbase+9, zero outside grid (2 passes) ----
    #pragma unroll
    for (int k = 0; k < 2; k++) {
        int idx = t + k * NTH;
        if (idx < 2 * XROWS * PW) {
            int c = idx / (XROWS * PW);
            int rem = idx - c * (XROWS * PW);
            int xr = rem / PW;
            int xc = rem - xr * PW;
            int gy = rbase - 2 + xr, gx = xc - 1;
            float v = 0.f;
            if ((unsigned)gy < 64u && (unsigned)gx < 64u)
                v = X[c * 4096 + gy * 64 + gx];
            Xs[c * XROWS * PW + xr * PW + xc] = v;
        }
    }
    __syncthreads();

    // ---- reward r over rows rbase-1..rbase+8 (1 pass; in-grid only) ----
    if (t < LROWS * 64) {
        int br = t >> 6, j = t & 63;
        int gy = rbase - 1 + br;
        if ((unsigned)gy < 64u) {
            float acc = weff[18];
            #pragma unroll
            for (int c = 0; c < 2; c++)
                #pragma unroll
                for (int ky = 0; ky < 3; ky++)
                    #pragma unroll
                    for (int kx = 0; kx < 3; kx++)
                        acc = fmaf(weff[c * 9 + ky * 3 + kx],
                                   Xs[c * XROWS * PW + (br + ky) * PW + j + kx],
                                   acc);
            rp[br * PW + j + 1] = acc;
        }
    }
    __syncthreads();

    // ---- qr = conv(r, Wq[:,0]) for own band: exactly 1 pass ----
    {
        uint64_t wrA[9], wrB[9];
        #pragma unroll
        for (int q = 0; q < 9; q++) {
            float wa = wqs[(2 * sub) * 18 + q];
            float wb = wqs[(2 * sub + 1) * 18 + q];
            wrA[q] = pack2(wa, wa);
            wrB[q] = pack2(wb, wb);
        }
        uint64_t a0 = 0ull, a1 = 0ull;
        #pragma unroll
        for (int ky = 0; ky < 3; ky++) {
            const uint64_t* rowp = (const uint64_t*)(rp + roff + ky * PW);
            uint64_t a01 = rowp[0], a23 = rowp[1];
            float2 f01 = unpack2(a01), f23 = unpack2(a23);
            uint64_t pm = pack2(f01.y, f23.x);
            a0 = fma2(wrA[ky * 3 + 0], a01, a0);
            a0 = fma2(wrA[ky * 3 + 1], pm,  a0);
            a0 = fma2(wrA[ky * 3 + 2], a23, a0);
            a1 = fma2(wrB[ky * 3 + 0], a01, a1);
            a1 = fma2(wrB[ky * 3 + 1], pm,  a1);
            a1 = fma2(wrB[ky * 3 + 2], a23, a1);
        }
        ulonglong2 qq; qq.x = a0; qq.y = a1;
        *(ulonglong2*)((uint64_t*)qr2 + sub * QSTR + qoff) = qq;
    }

    // v-channel weights (18 u64 = 36 regs, register-resident)
    uint64_t wpA[9], wpB[9];
    #pragma unroll
    for (int q = 0; q < 9; q++) {
        float wa = wqs[(2 * sub) * 18 + 9 + q];
        float wb = wqs[(2 * sub + 1) * 18 + 9 + q];
        wpA[q] = pack2(wa, wa);
        wpB[q] = pack2(wb, wb);
    }
    __syncthreads();
    cluster_sync();   // mbar init + zeroed buffers visible cluster-wide

    // ---- 19 VI sweeps, ONE pass each (it=0 reads zeros => v1 = max_a qr) ----
    float* cur = vbuf[0];
    float* nxt = vbuf[1];
    float* oth = vbuf[2];
    #pragma unroll 1
    for (int it = 0; it < NSWEEP; it++) {
        if (it > 0 && waiter) mbar_wait(mb, (it - 1) & 1);
        ulonglong2 qq = *(const ulonglong2*)(qr2s + qoff);
        uint64_t a0 = qq.x, a1 = qq.y;
        #pragma unroll
        for (int ky = 0; ky < 3; ky++) {
            const uint64_t* rowp = (const uint64_t*)(cur + roff + ky * PW);
            uint64_t a01 = rowp[0], a23 = rowp[1];
            float2 f01 = unpack2(a01), f23 = unpack2(a23);
            uint64_t pm = pack2(f01.y, f23.x);
            a0 = fma2(wpA[ky * 3 + 0], a01, a0);
            a0 = fma2(wpA[ky * 3 + 1], pm,  a0);
            a0 = fma2(wpA[ky * 3 + 2], a23, a0);
            a1 = fma2(wpB[ky * 3 + 0], a01, a1);
            a1 = fma2(wpB[ky * 3 + 1], pm,  a1);
            a1 = fma2(wpB[ky * 3 + 2], a23, a1);
        }
        float2 f0 = unpack2(a0), f1 = unpack2(a1);
        float v0 = fmaxf(f0.x, f1.x);
        float v1 = fmaxf(f0.y, f1.y);
        v0 = fmaxf(v0, __shfl_xor_sync(0xffffffffu, v0, 1));
        v1 = fmaxf(v1, __shfl_xor_sync(0xffffffffu, v1, 1));
        v0 = fmaxf(v0, __shfl_xor_sync(0xffffffffu, v0, 2));
        v1 = fmaxf(v1, __shfl_xor_sync(0xffffffffu, v1, 2));
        if (sub < 2) {
            float vs = (sub & 1) ? v1 : v0;
            nxt[soff] = vs;
            if (isTop) halo_out1(s2u(nxt + roffRT), (uint32_t)(rank - 1), vs, mb);
            if (isBot) halo_out1(s2u(nxt + roffRB), (uint32_t)(rank + 1), vs, mb);
        }
        __syncthreads();
        float* tmp = cur; cur = nxt; nxt = oth; oth = tmp;
    }
    cluster_sync();   // final halo pushes visible; no CTA exits early

    // ---- q at the 64 query points from v19 (exact halos), softmax ----
    if (t < 64) {
        int qi = S1[t], qj = S2[t];
        if ((qi >> 3) == rank) {
            int lr = qi - rbase;                  // buffer rows lr..lr+2
            float q[8];
            float m = -INFINITY;
            #pragma unroll
            for (int a = 0; a < 8; a++) {
                uint64_t qv = qr2[(a >> 1) * QSTR + (lr * 32 + (qj >> 1)) * 2 + (a & 1)];
                float2 f = unpack2(qv);
                float acc = (qj & 1) ? f.y : f.x;
                #pragma unroll
                for (int ky = 0; ky < 3; ky++)
                    #pragma unroll
                    for (int kx = 0; kx < 3; kx++)
                        acc = fmaf(wqs[a * 18 + 9 + ky * 3 + kx],
                                   cur[(lr + ky) * PW + qj + kx], acc);
                q[a] = acc;
                m = fmaxf(m, acc);
            }
            float s = 0.f;
            #pragma unroll
            for (int a = 0; a < 8; a++) { q[a] = expf(q[a] - m); s += q[a]; }
            float inv = 1.f / s;
            #pragma unroll
            for (int a = 0; a < 8; a++)
                out[t * 8 + a] = q[a] * inv;
        }
    }
}

extern "C" void kernel_launch(void* const* d_in, const int* in_sizes, int n_in,
                              void* d_out, int out_size)
{
    const float* X  = (const float*)d_in[0];   // [64,2,64,64] (batch 0 only)
    const int*   S1 = (const int*)d_in[1];     // [64]
    const int*   S2 = (const int*)d_in[2];     // [64]
    const float* Wh = (const float*)d_in[3];   // [150,2,3,3]
    const float* bh = (const float*)d_in[4];   // [150]
    const float* Wr = (const float*)d_in[5];   // [1,150,1,1]
    const float* Wq = (const float*)d_in[6];   // [8,2,3,3]
    float* out = (float*)d_out;                // [64,8]

    vin_kernel<<<NCL, NTH>>>(X, S1, S2, Wh, bh, Wr, Wq, out);
}

// round 17
// speedup vs baseline: 1.1724x; 1.1724x over previous
#include <cuda_runtime.h>
#include <math.h>
#include <stdint.h>

// VIN full-grid 8-CTA cluster, 512 threads: 8 rows x 32 col-pairs x 2 lanes
// = exactly one task per thread. 2 lanes per cell-pair, 4 actions per lane
// (36 packed f32x2 weight u64 = 72 regs, the footprint R4 proved resident),
// combined with ONE shfl.xor. Per-iteration halo exchange via
// st.shared::cluster + remote mbarrier.arrive.release; triple-buffered v
// makes cross-CTA skew-1 safe; final-sweep push + cluster_sync gives exact
// v19 at band edges. Only batch 0 reaches the output; 150-ch hidden conv
// collapses to a 2-ch 3x3 effective conv; qr precomputed once.

#define NCL 8
#define RPC 8
#define PW 66
#define LROWS 10               // band + 2 halo rows
#define XROWS 12               // X rows rbase-2 .. rbase+9
#define NTH 512
#define NSWEEP 19

__device__ __forceinline__ uint32_t s2u(const void* p) {
    return (uint32_t)__cvta_generic_to_shared(p);
}
__device__ __forceinline__ uint64_t pack2(float x, float y) {
    uint64_t r;
    asm("mov.b64 %0, {%1, %2};" : "=l"(r) : "f"(x), "f"(y));
    return r;
}
__device__ __forceinline__ float2 unpack2(uint64_t v) {
    float2 f;
    asm("mov.b64 {%0, %1}, %2;" : "=f"(f.x), "=f"(f.y) : "l"(v));
    return f;
}
__device__ __forceinline__ uint64_t fma2(uint64_t a, uint64_t b, uint64_t c) {
    uint64_t d;
    asm("fma.rn.f32x2 %0, %1, %2, %3;" : "=l"(d) : "l"(a), "l"(b), "l"(c));
    return d;
}
__device__ __forceinline__ void cluster_sync() {
    asm volatile("barrier.cluster.arrive.aligned;" ::: "memory");
    asm volatile("barrier.cluster.wait.aligned;" ::: "memory");
}
__device__ __forceinline__ void halo_out1(uint32_t laddr, uint32_t rank,
                                          float v, uint32_t lmbar) {
    asm volatile(
        "{\n\t.reg .b32 ra, rb;\n\t"
        "mapa.shared::cluster.u32 ra, %0, %1;\n\t"
        "st.shared::cluster.f32 [ra], %2;\n\t"
        "mapa.shared::cluster.u32 rb, %3, %1;\n\t"
        "mbarrier.arrive.release.cluster.shared::cluster.b64 _, [rb];\n\t}"
        :: "r"(laddr), "r"(rank), "f"(v), "r"(lmbar) : "memory");
}
__device__ __forceinline__ void mbar_wait(uint32_t addr, uint32_t parity) {
    asm volatile(
        "{\n\t.reg .pred P;\n\t"
        "W%=:\n\t"
        "mbarrier.try_wait.parity.acquire.cluster.shared::cta.b64 P, [%0], %1, 0x989680;\n\t"
        "@P bra D%=;\n\t"
        "bra W%=;\n\t"
        "D%=:\n\t}"
        :: "r"(addr), "r"(parity) : "memory");
}

__global__ __launch_bounds__(NTH, 1) __cluster_dims__(NCL, 1, 1)
void vin_kernel(const float* __restrict__ X,
                const int* __restrict__ S1,
                const int* __restrict__ S2,
                const float* __restrict__ Wh,
                const float* __restrict__ bh,
                const float* __restrict__ Wr,
                const float* __restrict__ Wq,
                float* __restrict__ out)
{
    // qr2[((row*32+p)*2 + half)*4 + i] : action half*4+i, cells (2p, 2p+1)
    __shared__ __align__(16) unsigned long long qr2[2048];
    __shared__ float Xs[2 * XROWS * PW];
    __shared__ float rp[LROWS * PW];
    __shared__ float vbuf[3][LROWS * PW];
    __shared__ float wqs[144];
    __shared__ float part[19 * 8];
    __shared__ float weff[19];
    __shared__ unsigned long long mbar;

    const int t = threadIdx.x;
    const int rank = blockIdx.x;
    const int rbase = rank * RPC;
    const int half = t & 1;                // actions half*4 .. half*4+3
    const int p = (t >> 1) & 31;           // pair: global cols 2p, 2p+1
    const int row = t >> 6;                // band row 0..7
    const uint32_t mb = s2u(&mbar);

    // task geometry, fully precomputed
    const int roff = row * PW + 2 * p;                   // read base
    const unsigned qbase = (unsigned)(((row * 32 + p) * 2 + half) * 4);
    const int soff = (row + 1) * PW + 1 + 2 * p + half;  // own cell store
    const bool isTop = (row == 0) && (rank > 0);
    const bool isBot = (row == RPC - 1) && (rank < NCL - 1);
    const bool waiter = isTop || ((row == RPC - 1) && (rank < NCL - 1));
    const int roffRT = 9 * PW + 1 + 2 * p + half;        // upper nbr bottom halo
    const int roffRB = 1 + 2 * p + half;                 // lower nbr top halo

    // ---- init ----
    for (int i = t; i < LROWS * PW; i += NTH) {
        vbuf[0][i] = 0.f; vbuf[1][i] = 0.f; vbuf[2][i] = 0.f; rp[i] = 0.f;
    }
    if (t < 144) wqs[t] = Wq[t];
    if (t < 152) {
        int pp = t >> 3, c = t & 7;
        float s = 0.f;
        for (int h = c; h < 150; h += 8)
            s += Wr[h] * (pp < 18 ? Wh[h * 18 + pp] : bh[h]);
        part[pp * 8 + c] = s;
    }
    if (t == 0) {
        int nb = (rank > 0) + (rank < NCL - 1);
        asm volatile("mbarrier.init.shared.b64 [%0], %1;"
                     :: "r"(mb), "r"(64 * nb) : "memory");
    }
    __syncthreads();
    if (t < 19) {
        float s = 0.f;
        #pragma unroll
        for (int c = 0; c < 8; c++) s += part[t * 8 + c];
        weff[t] = s;
    }
    // ---- X band rows rbase-2..rbase+9, zero outside grid ----
    for (int idx = t; idx < 2 * XROWS * PW; idx += NTH) {
        int c = idx / (XROWS * PW);
        int rem = idx - c * (XROWS * PW);
        int xr = rem / PW;
        int xc = rem - xr * PW;
        int gy = rbase - 2 + xr, gx = xc - 1;
        float v = 0.f;
        if ((unsigned)gy < 64u && (unsigned)gx < 64u)
            v = X[c * 4096 + gy * 64 + gx];
        Xs[c * XROWS * PW + xr * PW + xc] = v;
    }
    __syncthreads();

    // ---- reward r over rows rbase-1..rbase+8 (in-grid only) ----
    #pragma unroll
    for (int k = 0; k < 2; k++) {
        int idx = t + k * NTH;
        if (idx < LROWS * 64) {
            int br = idx >> 6, j = idx & 63;
            int gy = rbase - 1 + br;
            if ((unsigned)gy < 64u) {
                float acc = weff[18];
                #pragma unroll
                for (int c = 0; c < 2; c++)
                    #pragma unroll
                    for (int ky = 0; ky < 3; ky++)
                        #pragma unroll
                        for (int kx = 0; kx < 3; kx++)
                            acc = fmaf(weff[c * 9 + ky * 3 + kx],
                                       Xs[c * XROWS * PW + (br + ky) * PW + j + kx],
                                       acc);
                rp[br * PW + j + 1] = acc;
            }
        }
    }
    __syncthreads();

    // ---- qr = conv(r, Wq[:,0]) for own band: exactly 1 pass, 4 actions ----
    {
        uint64_t wr9[36];
        #pragma unroll
        for (int i = 0; i < 4; i++)
            #pragma unroll
            for (int q = 0; q < 9; q++) {
                float wv = wqs[(half * 4 + i) * 18 + q];
                wr9[i * 9 + q] = pack2(wv, wv);
            }
        uint64_t a0 = 0ull, a1 = 0ull, a2 = 0ull, a3 = 0ull;
        #pragma unroll
        for (int ky = 0; ky < 3; ky++) {
            const uint64_t* rowp = (const uint64_t*)(rp + roff + ky * PW);
            uint64_t d01 = rowp[0], d23 = rowp[1];
            float2 f01 = unpack2(d01), f23 = unpack2(d23);
            uint64_t pm = pack2(f01.y, f23.x);
            a0 = fma2(wr9[0 * 9 + ky * 3 + 0], d01, a0);
            a0 = fma2(wr9[0 * 9 + ky * 3 + 1], pm,  a0);
            a0 = fma2(wr9[0 * 9 + ky * 3 + 2], d23, a0);
            a1 = fma2(wr9[1 * 9 + ky * 3 + 0], d01, a1);
            a1 = fma2(wr9[1 * 9 + ky * 3 + 1], pm,  a1);
            a1 = fma2(wr9[1 * 9 + ky * 3 + 2], d23, a1);
            a2 = fma2(wr9[2 * 9 + ky * 3 + 0], d01, a2);
            a2 = fma2(wr9[2 * 9 + ky * 3 + 1], pm,  a2);
            a2 = fma2(wr9[2 * 9 + ky * 3 + 2], d23, a2);
            a3 = fma2(wr9[3 * 9 + ky * 3 + 0], d01, a3);
            a3 = fma2(wr9[3 * 9 + ky * 3 + 1], pm,  a3);
            a3 = fma2(wr9[3 * 9 + ky * 3 + 2], d23, a3);
        }
        ulonglong2 q01; q01.x = a0; q01.y = a1;
        ulonglong2 q23; q23.x = a2; q23.y = a3;
        *(ulonglong2*)(qr2 + qbase)     = q01;
        *(ulonglong2*)(qr2 + qbase + 2) = q23;
    }

    // v-channel weights for my 4 actions: 36 u64 = 72 regs (R4-proven budget)
    uint64_t wp[36];
    #pragma unroll
    for (int i = 0; i < 4; i++)
        #pragma unroll
        for (int q = 0; q < 9; q++) {
            float wv = wqs[(half * 4 + i) * 18 + 9 + q];
            wp[i * 9 + q] = pack2(wv, wv);
        }
    __syncthreads();
    cluster_sync();   // mbar init + zeroed buffers visible cluster-wide

    // ---- 19 VI sweeps, one task each (it=0 reads zeros => v1 = max_a qr) ----
    float* cur = vbuf[0];
    float* nxt = vbuf[1];
    float* oth = vbuf[2];
    #pragma unroll 1
    for (int it = 0; it < NSWEEP; it++) {
        if (it > 0 && waiter) mbar_wait(mb, (it - 1) & 1);
        ulonglong2 q01 = *(const ulonglong2*)(qr2 + qbase);
        ulonglong2 q23 = *(const ulonglong2*)(qr2 + qbase + 2);
        uint64_t a0 = q01.x, a1 = q01.y, a2 = q23.x, a3 = q23.y;
        #pragma unroll
        for (int ky = 0; ky < 3; ky++) {
            const uint64_t* rowp = (const uint64_t*)(cur + roff + ky * PW);
            uint64_t d01 = rowp[0], d23 = rowp[1];
            float2 f01 = unpack2(d01), f23 = unpack2(d23);
            uint64_t pm = pack2(f01.y, f23.x);
            a0 = fma2(wp[0 * 9 + ky * 3 + 0], d01, a0);
            a0 = fma2(wp[0 * 9 + ky * 3 + 1], pm,  a0);
            a0 = fma2(wp[0 * 9 + ky * 3 + 2], d23, a0);
            a1 = fma2(wp[1 * 9 + ky * 3 + 0], d01, a1);
            a1 = fma2(wp[1 * 9 + ky * 3 + 1], pm,  a1);
            a1 = fma2(wp[1 * 9 + ky * 3 + 2], d23, a1);
            a2 = fma2(wp[2 * 9 + ky * 3 + 0], d01, a2);
            a2 = fma2(wp[2 * 9 + ky * 3 + 1], pm,  a2);
            a2 = fma2(wp[2 * 9 + ky * 3 + 2], d23, a2);
            a3 = fma2(wp[3 * 9 + ky * 3 + 0], d01, a3);
            a3 = fma2(wp[3 * 9 + ky * 3 + 1], pm,  a3);
            a3 = fma2(wp[3 * 9 + ky * 3 + 2], d23, a3);
        }
        float2 f0 = unpack2(a0), f1 = unpack2(a1);
        float2 f2 = unpack2(a2), f3 = unpack2(a3);
        float v0 = fmaxf(fmaxf(f0.x, f1.x), fmaxf(f2.x, f3.x));
        float v1 = fmaxf(fmaxf(f0.y, f1.y), fmaxf(f2.y, f3.y));
        // combine the other 4 actions from the partner lane (xor 1)
        v0 = fmaxf(v0, __shfl_xor_sync(0xffffffffu, v0, 1));
        v1 = fmaxf(v1, __shfl_xor_sync(0xffffffffu, v1, 1));
        float vs = half ? v1 : v0;          // half0 -> cell 2p, half1 -> 2p+1
        nxt[soff] = vs;
        if (isTop) halo_out1(s2u(nxt + roffRT), (uint32_t)(rank - 1), vs, mb);
        if (isBot) halo_out1(s2u(nxt + roffRB), (uint32_t)(rank + 1), vs, mb);
        __syncthreads();
        float* tmp = cur; cur = nxt; nxt = oth; oth = tmp;
    }
    cluster_sync();   // final halo pushes visible; no CTA exits early

    // ---- q at the 64 query points from exact v19, softmax ----
    if (t < 64) {
        int qi = S1[t], qj = S2[t];
        if ((qi >> 3) == rank) {
            int lr = qi - rbase;            // buffer rows lr..lr+2
            float q[8];
            float m = -INFINITY;
            #pragma unroll
            for (int a = 0; a < 8; a++) {
                uint64_t qv = qr2[(((lr * 32 + (qj >> 1)) * 2 + (a >> 2)) * 4) + (a & 3)];
                float2 f = unpack2(qv);
                float acc = (qj & 1) ? f.y : f.x;
                #pragma unroll
                for (int ky = 0; ky < 3; ky++)
                    #pragma unroll
                    for (int kx = 0; kx < 3; kx++)
                        acc = fmaf(wqs[a * 18 + 9 + ky * 3 + kx],
                                   cur[(lr + ky) * PW + qj + kx], acc);
                q[a] = acc;
                m = fmaxf(m, acc);
            }
            float s = 0.f;
            #pragma unroll
            for (int a = 0; a < 8; a++) { q[a] = expf(q[a] - m); s += q[a]; }
            float inv = 1.f / s;
            #pragma unroll
            for (int a = 0; a < 8; a++)
                out[t * 8 + a] = q[a] * inv;
        }
    }
}

extern "C" void kernel_launch(void* const* d_in, const int* in_sizes, int n_in,
                              void* d_out, int out_size)
{
    const float* X  = (const float*)d_in[0];   // [64,2,64,64] (batch 0 only)
    const int*   S1 = (const int*)d_in[1];     // [64]
    const int*   S2 = (const int*)d_in[2];     // [64]
    const float* Wh = (const float*)d_in[3];   // [150,2,3,3]
    const float* bh = (const float*)d_in[4];   // [150]
    const float* Wr = (const float*)d_in[5];   // [1,150,1,1]
    const float* Wq = (const float*)d_in[6];   // [8,2,3,3]
    float* out = (float*)d_out;                // [64,8]

    vin_kernel<<<NCL, NTH>>>(X, S1, S2, Wh, bh, Wr, Wq, out);
}